// round 1
// baseline (speedup 1.0000x reference)
#include <cuda_runtime.h>
#include <math.h>

#define T_LEN 2048
#define BSZ   2
#define DMODEL 1024
#define NH    16
#define HDIM  64
#define EMB   1024           // NH*HDIM
#define MROWS 4096           // T_LEN*BSZ

// ---------------- scratch (allocation-free: device globals) ----------------
__device__ float g_q[(size_t)BSZ * NH * T_LEN * HDIM];   // [b][h][t][d]
__device__ float g_k[(size_t)BSZ * NH * T_LEN * HDIM];
__device__ float g_v[(size_t)BSZ * NH * T_LEN * HDIM];
__device__ float g_attn[(size_t)MROWS * EMB];            // [t*B+b][e]

// ============================================================================
// GEMM (TN): C[M,N] = A[M,K] @ W[N,K]^T (+bias). BM=BN=128, BK=16, 256 thr, 8x8.
// Both A and W are K-contiguous; tiles stored transposed in smem (pad +4).
// ============================================================================
#define BM 128
#define BN 128
#define BK 16
#define SPAD 4

// -------- QKV projection: z selects q/k/v; scatters to [b][h][t][d] --------
__global__ __launch_bounds__(256) void qkv_gemm(
    const float* __restrict__ Xq, const float* __restrict__ Xk,
    const float* __restrict__ Xv, const float* __restrict__ W,
    const float* __restrict__ bias)
{
    const int z = blockIdx.z;
    const float* A  = (z == 0) ? Xq : (z == 1) ? Xk : Xv;
    const float* Wz = W + (size_t)z * EMB * DMODEL;
    const float* bz = bias + (size_t)z * EMB;
    float* dst = (z == 0) ? g_q : (z == 1) ? g_k : g_v;

    __shared__ float As[BK][BM + SPAD];
    __shared__ float Ws[BK][BN + SPAD];

    const int tid = threadIdx.x;
    const int tx = tid & 15;          // N direction (16)
    const int ty = tid >> 4;          // M direction (16)
    const int m0 = blockIdx.y * BM;
    const int n0 = blockIdx.x * BN;

    float acc[8][8];
    #pragma unroll
    for (int i = 0; i < 8; i++)
        #pragma unroll
        for (int j = 0; j < 8; j++) acc[i][j] = 0.f;

    for (int k0 = 0; k0 < DMODEL; k0 += BK) {
        #pragma unroll
        for (int it = 0; it < 2; it++) {
            int idx = tid + it * 256;        // 0..511
            int row = idx >> 2;              // 0..127
            int c4  = (idx & 3) << 2;        // 0,4,8,12
            float4 a = *(const float4*)(A  + (size_t)(m0 + row) * DMODEL + k0 + c4);
            As[c4 + 0][row] = a.x; As[c4 + 1][row] = a.y;
            As[c4 + 2][row] = a.z; As[c4 + 3][row] = a.w;
            float4 w = *(const float4*)(Wz + (size_t)(n0 + row) * DMODEL + k0 + c4);
            Ws[c4 + 0][row] = w.x; Ws[c4 + 1][row] = w.y;
            Ws[c4 + 2][row] = w.z; Ws[c4 + 3][row] = w.w;
        }
        __syncthreads();
        #pragma unroll
        for (int k = 0; k < BK; k++) {
            float af[8], wf[8];
            *(float4*)&af[0] = *(const float4*)&As[k][ty * 8];
            *(float4*)&af[4] = *(const float4*)&As[k][ty * 8 + 4];
            *(float4*)&wf[0] = *(const float4*)&Ws[k][tx * 8];
            *(float4*)&wf[4] = *(const float4*)&Ws[k][tx * 8 + 4];
            #pragma unroll
            for (int i = 0; i < 8; i++)
                #pragma unroll
                for (int j = 0; j < 8; j++)
                    acc[i][j] = fmaf(af[i], wf[j], acc[i][j]);
        }
        __syncthreads();
    }

    const float scale = (z == 0) ? 0.125f : 1.0f;   // HD^-0.5 = 64^-0.5
    #pragma unroll
    for (int i = 0; i < 8; i++) {
        int m = m0 + ty * 8 + i;
        int t = m >> 1;           // B=2
        int b = m & 1;
        #pragma unroll
        for (int j = 0; j < 8; j += 4) {
            int n = n0 + tx * 8 + j;
            int h = n >> 6;       // /HDIM
            int d = n & 63;
            float4 r;
            r.x = (acc[i][j + 0] + __ldg(&bz[n + 0])) * scale;
            r.y = (acc[i][j + 1] + __ldg(&bz[n + 1])) * scale;
            r.z = (acc[i][j + 2] + __ldg(&bz[n + 2])) * scale;
            r.w = (acc[i][j + 3] + __ldg(&bz[n + 3])) * scale;
            *(float4*)(dst + (((size_t)(b * NH + h) * T_LEN + t) * HDIM + d)) = r;
        }
    }
}

// -------- Output projection: C = g_attn @ Wo^T + bo, plain layout ----------
__global__ __launch_bounds__(256) void out_gemm(
    const float* __restrict__ W, const float* __restrict__ bias,
    float* __restrict__ C)
{
    const float* A = g_attn;

    __shared__ float As[BK][BM + SPAD];
    __shared__ float Ws[BK][BN + SPAD];

    const int tid = threadIdx.x;
    const int tx = tid & 15;
    const int ty = tid >> 4;
    const int m0 = blockIdx.y * BM;
    const int n0 = blockIdx.x * BN;

    float acc[8][8];
    #pragma unroll
    for (int i = 0; i < 8; i++)
        #pragma unroll
        for (int j = 0; j < 8; j++) acc[i][j] = 0.f;

    for (int k0 = 0; k0 < EMB; k0 += BK) {
        #pragma unroll
        for (int it = 0; it < 2; it++) {
            int idx = tid + it * 256;
            int row = idx >> 2;
            int c4  = (idx & 3) << 2;
            float4 a = *(const float4*)(A + (size_t)(m0 + row) * EMB + k0 + c4);
            As[c4 + 0][row] = a.x; As[c4 + 1][row] = a.y;
            As[c4 + 2][row] = a.z; As[c4 + 3][row] = a.w;
            float4 w = *(const float4*)(W + (size_t)(n0 + row) * EMB + k0 + c4);
            Ws[c4 + 0][row] = w.x; Ws[c4 + 1][row] = w.y;
            Ws[c4 + 2][row] = w.z; Ws[c4 + 3][row] = w.w;
        }
        __syncthreads();
        #pragma unroll
        for (int k = 0; k < BK; k++) {
            float af[8], wf[8];
            *(float4*)&af[0] = *(const float4*)&As[k][ty * 8];
            *(float4*)&af[4] = *(const float4*)&As[k][ty * 8 + 4];
            *(float4*)&wf[0] = *(const float4*)&Ws[k][tx * 8];
            *(float4*)&wf[4] = *(const float4*)&Ws[k][tx * 8 + 4];
            #pragma unroll
            for (int i = 0; i < 8; i++)
                #pragma unroll
                for (int j = 0; j < 8; j++)
                    acc[i][j] = fmaf(af[i], wf[j], acc[i][j]);
        }
        __syncthreads();
    }

    #pragma unroll
    for (int i = 0; i < 8; i++) {
        int m = m0 + ty * 8 + i;
        #pragma unroll
        for (int j = 0; j < 8; j += 4) {
            int n = n0 + tx * 8 + j;
            float4 r;
            r.x = acc[i][j + 0] + __ldg(&bias[n + 0]);
            r.y = acc[i][j + 1] + __ldg(&bias[n + 1]);
            r.z = acc[i][j + 2] + __ldg(&bias[n + 2]);
            r.w = acc[i][j + 3] + __ldg(&bias[n + 3]);
            *(float4*)(C + (size_t)m * DMODEL + n) = r;
        }
    }
}

// ============================================================================
// Flash attention: one CTA = (128 query rows, one (b,h)). 1 row/thread.
// q + O accumulator in registers; K/V 64x64 tiles in smem (broadcast float4
// reads); online softmax in groups of 8 keys. Mask read straight from gmem
// (16 MB, fully L2-resident after first head).
// ============================================================================
__global__ __launch_bounds__(128) void flash_attn(const float* __restrict__ mask,
                                                  float* __restrict__ attn_out)
{
    __shared__ float Ks[64 * 64];
    __shared__ float Vs[64 * 64];

    const int bh = blockIdx.y;                       // b*NH + h
    const int t  = blockIdx.x * 128 + threadIdx.x;   // global query row

    const float* qp = g_q + ((size_t)bh * T_LEN + t) * HDIM;
    float q[64];
    #pragma unroll
    for (int d = 0; d < 64; d += 4)
        *(float4*)&q[d] = *(const float4*)(qp + d);

    float o[64];
    #pragma unroll
    for (int d = 0; d < 64; d++) o[d] = 0.f;
    float mmax = -1e30f, l = 0.f;

    const float* kb   = g_k + (size_t)bh * T_LEN * HDIM;
    const float* vb   = g_v + (size_t)bh * T_LEN * HDIM;
    const float* mrow = mask + (size_t)t * T_LEN;

    for (int s0 = 0; s0 < T_LEN; s0 += 64) {
        __syncthreads();
        #pragma unroll
        for (int i = threadIdx.x; i < 64 * 64 / 4; i += 128) {
            ((float4*)Ks)[i] = ((const float4*)(kb + (size_t)s0 * HDIM))[i];
            ((float4*)Vs)[i] = ((const float4*)(vb + (size_t)s0 * HDIM))[i];
        }
        __syncthreads();

        #pragma unroll 1
        for (int g = 0; g < 64; g += 8) {
            float s[8];
            #pragma unroll
            for (int j = 0; j < 8; j++) {
                const float* kr = Ks + (g + j) * 64;
                float a0 = 0.f, a1 = 0.f, a2 = 0.f, a3 = 0.f;
                #pragma unroll
                for (int d = 0; d < 64; d += 4) {
                    float4 kv = *(const float4*)(kr + d);
                    a0 = fmaf(q[d + 0], kv.x, a0);
                    a1 = fmaf(q[d + 1], kv.y, a1);
                    a2 = fmaf(q[d + 2], kv.z, a2);
                    a3 = fmaf(q[d + 3], kv.w, a3);
                }
                s[j] = (a0 + a1) + (a2 + a3);
            }
            // additive mask
            float4 mv0 = *(const float4*)(mrow + s0 + g);
            float4 mv1 = *(const float4*)(mrow + s0 + g + 4);
            s[0] += mv0.x; s[1] += mv0.y; s[2] += mv0.z; s[3] += mv0.w;
            s[4] += mv1.x; s[5] += mv1.y; s[6] += mv1.z; s[7] += mv1.w;

            // online softmax update
            float tmax = mmax;
            #pragma unroll
            for (int j = 0; j < 8; j++) tmax = fmaxf(tmax, s[j]);
            float corr = __expf(mmax - tmax);
            mmax = tmax;
            l *= corr;
            #pragma unroll
            for (int d = 0; d < 64; d++) o[d] *= corr;

            float p[8];
            #pragma unroll
            for (int j = 0; j < 8; j++) { p[j] = __expf(s[j] - tmax); l += p[j]; }

            #pragma unroll
            for (int j = 0; j < 8; j++) {
                const float* vr = Vs + (g + j) * 64;
                #pragma unroll
                for (int d = 0; d < 64; d += 4) {
                    float4 vv = *(const float4*)(vr + d);
                    o[d + 0] = fmaf(p[j], vv.x, o[d + 0]);
                    o[d + 1] = fmaf(p[j], vv.y, o[d + 1]);
                    o[d + 2] = fmaf(p[j], vv.z, o[d + 2]);
                    o[d + 3] = fmaf(p[j], vv.w, o[d + 3]);
                }
            }
        }
    }

    const float inv = 1.0f / l;
    const int b = bh / NH, h = bh % NH;
    float* dst = attn_out + ((size_t)t * BSZ + b) * EMB + h * HDIM;
    #pragma unroll
    for (int d = 0; d < 64; d += 4) {
        float4 r;
        r.x = o[d + 0] * inv; r.y = o[d + 1] * inv;
        r.z = o[d + 2] * inv; r.w = o[d + 3] * inv;
        *(float4*)(dst + d) = r;
    }
}

// ============================================================================
// Launch
// ============================================================================
extern "C" void kernel_launch(void* const* d_in, const int* in_sizes, int n_in,
                              void* d_out, int out_size)
{
    const float* query  = (const float*)d_in[0];
    const float* key    = (const float*)d_in[1];
    const float* value  = (const float*)d_in[2];
    const float* mask   = (const float*)d_in[3];
    const float* in_w   = (const float*)d_in[4];
    const float* in_b   = (const float*)d_in[5];
    const float* out_w  = (const float*)d_in[6];
    const float* out_b  = (const float*)d_in[7];
    float* out = (float*)d_out;

    float* attn_ptr;
    cudaGetSymbolAddress((void**)&attn_ptr, g_attn);

    // 1) QKV projection (z = 0/1/2 -> q/k/v), scatter to per-head layout
    qkv_gemm<<<dim3(EMB / BN, MROWS / BM, 3), 256>>>(query, key, value, in_w, in_b);

    // 2) Attention (32 (b,h) heads x 16 query tiles)
    flash_attn<<<dim3(T_LEN / 128, BSZ * NH), 128>>>(mask, attn_ptr);

    // 3) Output projection directly into d_out
    out_gemm<<<dim3(DMODEL / BN, MROWS / BM), 256>>>(out_w, out_b, out);
}